// round 7
// baseline (speedup 1.0000x reference)
#include <cuda_runtime.h>
#include <cstdint>

#define LOG2E 1.4426950408889634f

// ---- f32x2 packed helpers (sm_100a) ----
__device__ __forceinline__ unsigned long long pk2(float lo, float hi) {
    unsigned long long r;
    asm("mov.b64 %0, {%1, %2};" : "=l"(r) : "f"(lo), "f"(hi));
    return r;
}
__device__ __forceinline__ void upk2(unsigned long long v, float& lo, float& hi) {
    asm("mov.b64 {%0, %1}, %2;" : "=f"(lo), "=f"(hi) : "l"(v));
}
__device__ __forceinline__ unsigned long long ffma2(unsigned long long a,
                                                    unsigned long long b,
                                                    unsigned long long c) {
    unsigned long long d;
    asm("fma.rn.f32x2 %0, %1, %2, %3;" : "=l"(d) : "l"(a), "l"(b), "l"(c));
    return d;
}
__device__ __forceinline__ unsigned long long fadd2(unsigned long long a,
                                                    unsigned long long b) {
    unsigned long long d;
    asm("add.rn.f32x2 %0, %1, %2;" : "=l"(d) : "l"(a), "l"(b));
    return d;
}
__device__ __forceinline__ unsigned long long fmul2(unsigned long long a,
                                                    unsigned long long b) {
    unsigned long long d;
    asm("mul.rn.f32x2 %0, %1, %2;" : "=l"(d) : "l"(a), "l"(b));
    return d;
}
__device__ __forceinline__ float ex2f(float x) {
    float r;
    asm("ex2.approx.f32 %0, %1;" : "=f"(r) : "f"(x));
    return r;
}
__device__ __forceinline__ float rcpf(float x) {
    float r;
    asm("rcp.approx.f32 %0, %1;" : "=f"(r) : "f"(x));
    return r;
}
__device__ __forceinline__ float rsqf(float x) {
    float r;
    asm("rsqrt.approx.f32 %0, %1;" : "=f"(r) : "f"(x));
    return r;
}

__global__ __launch_bounds__(256)
void gat_main(const float* __restrict__ h, const float* __restrict__ W,
              const float* __restrict__ a, const float* __restrict__ Bp,
              float* __restrict__ out) {
    // paired layouts: [v][wlow] float2 = (val@w, val@w+32), pitch 33 float2
    __shared__ float2 sE1p[32 * 33];
    __shared__ float2 sE2p[32 * 33];
    __shared__ float2 sSp[32 * 33];
    // per-warp hs staging: [v] stride 6 float2; slots = (t,t+4) pairs
    __shared__ __align__(16) float2 sHS[8 * 32 * 6];
    // Wt pre-paired over o-pairs: sWtp[op*8+t] = (W[t,2op], W[t,2op+1])
    __shared__ __align__(16) unsigned long long sWtp[64];
    __shared__ float sWa[16];  // (W@a1, W@a2) per t, *LOG2E

    const int tid = threadIdx.x;
    const int lane = tid & 31;
    const int warp = tid >> 5;
    const int hh = blockIdx.x;
    const int n = blockIdx.y;

    const float* hblk = h + ((size_t)(n * 64 + hh)) * 16384;  // [w][t][v]

    // ---- inline setup: Wt pairs + Wa (replaces setup_kernel) ----
    if (tid < 64) {
        int op = tid >> 3, t = tid & 7;
        float2 wp = *(const float2*)(W + t * 16 + 2 * op);
        sWtp[tid] = pk2(wp.x, wp.y);
    }
    if (tid < 16) {
        int which = tid >> 3, t = tid & 7;
        float acc = 0.0f;
#pragma unroll
        for (int o = 0; o < 16; o++) acc += W[t * 16 + o] * a[which * 16 + o];
        sWa[tid] = acc * LOG2E;  // pre-scale so exp() becomes bare ex2
    }
    __syncthreads();

    float wa1[8], wa2[8];
#pragma unroll
    for (int t = 0; t < 8; t++) {
        wa1[t] = sWa[t];
        wa2[t] = sWa[8 + t];
    }

    // -------- Phase 1: e1/e2 = h . (W a * log2e) over t --------
#pragma unroll
    for (int r = 0; r < 2; r++) {
        int qi = tid + 256 * r;  // 0..511
        int w = qi >> 3;
        int v4 = qi & 7;
        const float4* p = (const float4*)(hblk + w * 256 + v4 * 4);
        float4 a1 = make_float4(0.f, 0.f, 0.f, 0.f);
        float4 a2 = make_float4(0.f, 0.f, 0.f, 0.f);
#pragma unroll
        for (int t = 0; t < 8; t++) {
            float4 x = __ldg(p + t * 8);
            a1.x = fmaf(x.x, wa1[t], a1.x);
            a1.y = fmaf(x.y, wa1[t], a1.y);
            a1.z = fmaf(x.z, wa1[t], a1.z);
            a1.w = fmaf(x.w, wa1[t], a1.w);
            a2.x = fmaf(x.x, wa2[t], a2.x);
            a2.y = fmaf(x.y, wa2[t], a2.y);
            a2.z = fmaf(x.z, wa2[t], a2.z);
            a2.w = fmaf(x.w, wa2[t], a2.w);
        }
        int wl = w & 31, whf = w >> 5;
        int vb = v4 * 4;
        ((float*)&sE1p[(vb + 0) * 33 + wl])[whf] = a1.x;
        ((float*)&sE1p[(vb + 1) * 33 + wl])[whf] = a1.y;
        ((float*)&sE1p[(vb + 2) * 33 + wl])[whf] = a1.z;
        ((float*)&sE1p[(vb + 3) * 33 + wl])[whf] = a1.w;
        ((float*)&sE2p[(vb + 0) * 33 + wl])[whf] = a2.x;
        ((float*)&sE2p[(vb + 1) * 33 + wl])[whf] = a2.y;
        ((float*)&sE2p[(vb + 2) * 33 + wl])[whf] = a2.z;
        ((float*)&sE2p[(vb + 3) * 33 + wl])[whf] = a2.w;
    }
    __syncthreads();

    // -------- Phase 2: att_sum[i][w] = sum_j softmax_w(leaky(e1[i]+e2[j])) --------
    {
        unsigned long long E1p[4], att2[4];
#pragma unroll
        for (int ii = 0; ii < 4; ii++) {
            E1p[ii] = *(const unsigned long long*)&sE1p[(warp + ii * 8) * 33 + lane];
            att2[ii] = 0ull;
        }
        const unsigned long long DUP02 = pk2(0.2f, 0.2f);

        for (int j = 0; j < 32; j++) {
            unsigned long long e2 = *(const unsigned long long*)&sE2p[j * 33 + lane];
            unsigned long long T2[4];
            float Z[4];
#pragma unroll
            for (int ii = 0; ii < 4; ii++) {
                unsigned long long x2 = fadd2(E1p[ii], e2);
                unsigned long long m2 = fmul2(x2, DUP02);
                float x0, x1, m0, m1;
                upk2(x2, x0, x1);
                upk2(m2, m0, m1);
                x0 = fmaxf(x0, m0);  // leaky relu (log2-scaled domain)
                x1 = fmaxf(x1, m1);
                float t0 = ex2f(x0);
                float t1 = ex2f(x1);
                T2[ii] = pk2(t0, t1);
                Z[ii] = t0 + t1;
            }
            // 4 independent scalar butterflies, advanced level-by-level (ILP=4)
#pragma unroll
            for (int off = 16; off > 0; off >>= 1) {
#pragma unroll
                for (int ii = 0; ii < 4; ii++)
                    Z[ii] += __shfl_xor_sync(0xffffffffu, Z[ii], off);
            }
#pragma unroll
            for (int ii = 0; ii < 4; ii++) {
                float inv = rcpf(Z[ii]);
                att2[ii] = ffma2(T2[ii], pk2(inv, inv), att2[ii]);
            }
        }
#pragma unroll
        for (int ii = 0; ii < 4; ii++)
            *(unsigned long long*)&sSp[(warp + ii * 8) * 33 + lane] = att2[ii];
    }
    __syncthreads();

    // ---- inline adjacency normalization (per-warp, redundant, L1-hot) ----
    // lane = u. Row pass (lane = row): min/max + row sum; column pass for adjc.
    float adjc[32];
    {
        float rsum = 0.0f, mn = 1e30f, mx = -1e30f;
#pragma unroll 8
        for (int k = 0; k < 32; k++) {
            float v = __ldg(Bp + lane * 32 + k) + ((k == lane) ? 1.0f : 0.0f);
            rsum += v;
            mn = fminf(mn, v);
            mx = fmaxf(mx, v);
        }
#pragma unroll
        for (int off = 16; off > 0; off >>= 1) {
            mn = fminf(mn, __shfl_xor_sync(0xffffffffu, mn, off));
            mx = fmaxf(mx, __shfl_xor_sync(0xffffffffu, mx, off));
        }
        float scale = rcpf(mx - mn);
        float dinv_l = rsqf((rsum - 32.0f * mn) * scale);
#pragma unroll
        for (int v = 0; v < 32; v++) {
            float raw = __ldg(Bp + v * 32 + lane) + ((v == lane) ? 1.0f : 0.0f);
            float dv = __shfl_sync(0xffffffffu, dinv_l, v);
            adjc[v] = dv * ((raw - mn) * scale) * dinv_l;
        }
    }

    // -------- Phase 3: out[o,u] = sum_t Wt[o,t] * (sum_v hs[w,t,v]*adj[v,u]) --------
    float2* myhs = sHS + warp * 32 * 6;

    for (int k = 0; k < 8; k++) {
        int w = warp * 8 + k;
        float sv = ((const float*)&sSp[lane * 33 + (w & 31)])[w >> 5];
        const float* hw = hblk + w * 256 + lane;
        float hs0 = __ldg(hw + 0 * 32) * sv;
        float hs1 = __ldg(hw + 1 * 32) * sv;
        float hs2 = __ldg(hw + 2 * 32) * sv;
        float hs3 = __ldg(hw + 3 * 32) * sv;
        float hs4 = __ldg(hw + 4 * 32) * sv;
        float hs5 = __ldg(hw + 5 * 32) * sv;
        float hs6 = __ldg(hw + 6 * 32) * sv;
        float hs7 = __ldg(hw + 7 * 32) * sv;
        *(float4*)(myhs + lane * 6) = make_float4(hs0, hs4, hs1, hs5);
        *(float4*)(myhs + lane * 6 + 2) = make_float4(hs2, hs6, hs3, hs7);
        __syncwarp();

        unsigned long long g0 = 0ull, g1 = 0ull, g2 = 0ull, g3 = 0ull;
#pragma unroll
        for (int v = 0; v < 32; v++) {
            ulonglong2 q0 = *(const ulonglong2*)(myhs + v * 6);
            ulonglong2 q1 = *(const ulonglong2*)(myhs + v * 6 + 2);
            unsigned long long ad = pk2(adjc[v], adjc[v]);
            g0 = ffma2(q0.x, ad, g0);  // (t0,t4)
            g1 = ffma2(q0.y, ad, g1);  // (t1,t5)
            g2 = ffma2(q1.x, ad, g2);  // (t2,t6)
            g3 = ffma2(q1.y, ad, g3);  // (t3,t7)
        }
        float G0, G1, G2, G3, G4, G5, G6, G7;
        upk2(g0, G0, G4);
        upk2(g1, G1, G5);
        upk2(g2, G2, G6);
        upk2(g3, G3, G7);
        unsigned long long dG[8];
        dG[0] = pk2(G0, G0); dG[1] = pk2(G1, G1);
        dG[2] = pk2(G2, G2); dG[3] = pk2(G3, G3);
        dG[4] = pk2(G4, G4); dG[5] = pk2(G5, G5);
        dG[6] = pk2(G6, G6); dG[7] = pk2(G7, G7);

        float* op = out + ((size_t)(n * 64 + w) * 64 + hh) * 512 + lane;
#pragma unroll
        for (int o2 = 0; o2 < 8; o2++) {
            const ulonglong2* wt = (const ulonglong2*)(sWtp + o2 * 8);
            ulonglong2 wA = wt[0], wB = wt[1], wC = wt[2], wD = wt[3];
            unsigned long long acc = fmul2(dG[0], wA.x);
            acc = ffma2(dG[1], wA.y, acc);
            acc = ffma2(dG[2], wB.x, acc);
            acc = ffma2(dG[3], wB.y, acc);
            acc = ffma2(dG[4], wC.x, acc);
            acc = ffma2(dG[5], wC.y, acc);
            acc = ffma2(dG[6], wD.x, acc);
            acc = ffma2(dG[7], wD.y, acc);
            float r0, r1;
            upk2(acc, r0, r1);
            float e0 = r0 > 0.0f ? r0 : ex2f(r0 * LOG2E) - 1.0f;  // elu
            float e1 = r1 > 0.0f ? r1 : ex2f(r1 * LOG2E) - 1.0f;
            op[(2 * o2) * 32] = e0;
            op[(2 * o2 + 1) * 32] = e1;
        }
        __syncwarp();
    }
}

extern "C" void kernel_launch(void* const* d_in, const int* in_sizes, int n_in,
                              void* d_out, int out_size) {
    const float* h = (const float*)d_in[0];   // (8,64,64,8,32)
    const float* W = (const float*)d_in[1];   // (8,16)
    const float* a = (const float*)d_in[2];   // (32,1)
    const float* Bp = (const float*)d_in[3];  // (32,32)
    float* out = (float*)d_out;               // (8,64,64,16,32)

    dim3 grid(64, 8);
    gat_main<<<grid, 256>>>(h, W, a, Bp, out);
}

// round 8
// speedup vs baseline: 1.2526x; 1.2526x over previous
#include <cuda_runtime.h>
#include <cstdint>

#define LOG2E 1.4426950408889634f

// ---- f32x2 packed helpers (sm_100a) ----
__device__ __forceinline__ unsigned long long pk2(float lo, float hi) {
    unsigned long long r;
    asm("mov.b64 %0, {%1, %2};" : "=l"(r) : "f"(lo), "f"(hi));
    return r;
}
__device__ __forceinline__ void upk2(unsigned long long v, float& lo, float& hi) {
    asm("mov.b64 {%0, %1}, %2;" : "=f"(lo), "=f"(hi) : "l"(v));
}
__device__ __forceinline__ unsigned long long ffma2(unsigned long long a,
                                                    unsigned long long b,
                                                    unsigned long long c) {
    unsigned long long d;
    asm("fma.rn.f32x2 %0, %1, %2, %3;" : "=l"(d) : "l"(a), "l"(b), "l"(c));
    return d;
}
__device__ __forceinline__ unsigned long long fadd2(unsigned long long a,
                                                    unsigned long long b) {
    unsigned long long d;
    asm("add.rn.f32x2 %0, %1, %2;" : "=l"(d) : "l"(a), "l"(b));
    return d;
}
__device__ __forceinline__ unsigned long long fmul2(unsigned long long a,
                                                    unsigned long long b) {
    unsigned long long d;
    asm("mul.rn.f32x2 %0, %1, %2;" : "=l"(d) : "l"(a), "l"(b));
    return d;
}
__device__ __forceinline__ float ex2f(float x) {
    float r;
    asm("ex2.approx.f32 %0, %1;" : "=f"(r) : "f"(x));
    return r;
}
__device__ __forceinline__ float rcpf(float x) {
    float r;
    asm("rcp.approx.f32 %0, %1;" : "=f"(r) : "f"(x));
    return r;
}
__device__ __forceinline__ float rsqf(float x) {
    float r;
    asm("rsqrt.approx.f32 %0, %1;" : "=f"(r) : "f"(x));
    return r;
}

__global__ __launch_bounds__(256)
void gat_main(const float* __restrict__ h, const float* __restrict__ W,
              const float* __restrict__ a, const float* __restrict__ Bp,
              float* __restrict__ out) {
    // paired layouts: [v][wlow] float2 = (val@w, val@w+32), pitch 33 float2
    __shared__ float2 sE1p[32 * 33];
    __shared__ float2 sE2p[32 * 33];
    __shared__ float2 sSp[32 * 33];
    // per-warp hs staging: [v] stride 6 float2; slots = (t,t+4) pairs
    __shared__ __align__(16) float2 sHS[8 * 32 * 6];
    // Wt pre-paired over o-pairs: sWtp[op*8+t] = (W[t,2op], W[t,2op+1])
    __shared__ __align__(16) unsigned long long sWtp[64];
    __shared__ float sWa[16];   // (W@a1, W@a2) per t, *LOG2E
    __shared__ float sAdj[32 * 33];  // normalized adjacency, [v][u], pitch 33
    __shared__ float sRedMin[8], sRedMax[8];

    const int tid = threadIdx.x;
    const int lane = tid & 31;
    const int warp = tid >> 5;
    const int hh = blockIdx.x;
    const int n = blockIdx.y;

    const float* hblk = h + ((size_t)(n * 64 + hh)) * 16384;  // [w][t][v]

    // ---- inline setup A: Wt pairs + Wa ----
    if (tid < 64) {
        int op = tid >> 3, t = tid & 7;
        float2 wp = *(const float2*)(W + t * 16 + 2 * op);
        sWtp[tid] = pk2(wp.x, wp.y);
    }
    if (tid < 16) {
        int which = tid >> 3, t = tid & 7;
        float acc = 0.0f;
#pragma unroll
        for (int o = 0; o < 16; o++) acc += W[t * 16 + o] * a[which * 16 + o];
        sWa[tid] = acc * LOG2E;  // pre-scale so exp() becomes bare ex2
    }

    // ---- inline setup B: adjacency, cooperative + coalesced ----
    {
        // 1 float4 per thread: elements 4*tid .. 4*tid+3; row = tid>>3
        float4 bq = __ldg((const float4*)Bp + tid);
        int row = tid >> 3;
        int c0 = (tid & 7) * 4;
        bq.x += (c0 + 0 == row) ? 1.0f : 0.0f;
        bq.y += (c0 + 1 == row) ? 1.0f : 0.0f;
        bq.z += (c0 + 2 == row) ? 1.0f : 0.0f;
        bq.w += (c0 + 3 == row) ? 1.0f : 0.0f;
        // stash raw values (pitch-33 rows; 4-col groups stay in-row)
        sAdj[row * 33 + c0 + 0] = bq.x;
        sAdj[row * 33 + c0 + 1] = bq.y;
        sAdj[row * 33 + c0 + 2] = bq.z;
        sAdj[row * 33 + c0 + 3] = bq.w;

        float mn = fminf(fminf(bq.x, bq.y), fminf(bq.z, bq.w));
        float mx = fmaxf(fmaxf(bq.x, bq.y), fmaxf(bq.z, bq.w));
#pragma unroll
        for (int off = 16; off > 0; off >>= 1) {
            mn = fminf(mn, __shfl_xor_sync(0xffffffffu, mn, off));
            mx = fmaxf(mx, __shfl_xor_sync(0xffffffffu, mx, off));
        }
        if (lane == 0) {
            sRedMin[warp] = mn;
            sRedMax[warp] = mx;
        }
        __syncthreads();
        float m0 = sRedMin[lane & 7], m1 = sRedMax[lane & 7];
#pragma unroll
        for (int off = 4; off > 0; off >>= 1) {
            m0 = fminf(m0, __shfl_xor_sync(0xffffffffu, m0, off));
            m1 = fmaxf(m1, __shfl_xor_sync(0xffffffffu, m1, off));
        }
        mn = m0;  // now uniform across the warp (lanes 0..7 reduced, bfly covers all)
        mx = m1;
        float scale = rcpf(mx - mn);

        // row sums (raw) — lane = row, conflict-free stride-33 LDS; all warps redundant
        float rsum = 0.0f;
#pragma unroll 8
        for (int k = 0; k < 32; k++) rsum += sAdj[lane * 33 + k];
        float dinv_l = rsqf((rsum - 32.0f * mn) * scale);

        // normalize this thread's 4 entries
        float dv_r = __shfl_sync(0xffffffffu, dinv_l, row & 31);
        // NOTE: row is 0..31 and identical for the thread's 4 entries
        float dv0 = __shfl_sync(0xffffffffu, dinv_l, c0 + 0);
        float dv1 = __shfl_sync(0xffffffffu, dinv_l, c0 + 1);
        float dv2 = __shfl_sync(0xffffffffu, dinv_l, c0 + 2);
        float dv3 = __shfl_sync(0xffffffffu, dinv_l, c0 + 3);
        __syncthreads();  // everyone done reading raw sAdj rows
        sAdj[row * 33 + c0 + 0] = dv_r * ((bq.x - mn) * scale) * dv0;
        sAdj[row * 33 + c0 + 1] = dv_r * ((bq.y - mn) * scale) * dv1;
        sAdj[row * 33 + c0 + 2] = dv_r * ((bq.z - mn) * scale) * dv2;
        sAdj[row * 33 + c0 + 3] = dv_r * ((bq.w - mn) * scale) * dv3;
    }
    __syncthreads();

    float wa1[8], wa2[8];
#pragma unroll
    for (int t = 0; t < 8; t++) {
        wa1[t] = sWa[t];
        wa2[t] = sWa[8 + t];
    }

    // -------- Phase 1: e1/e2 = h . (W a * log2e) over t --------
#pragma unroll
    for (int r = 0; r < 2; r++) {
        int qi = tid + 256 * r;  // 0..511
        int w = qi >> 3;
        int v4 = qi & 7;
        const float4* p = (const float4*)(hblk + w * 256 + v4 * 4);
        float4 a1 = make_float4(0.f, 0.f, 0.f, 0.f);
        float4 a2 = make_float4(0.f, 0.f, 0.f, 0.f);
#pragma unroll
        for (int t = 0; t < 8; t++) {
            float4 x = __ldg(p + t * 8);
            a1.x = fmaf(x.x, wa1[t], a1.x);
            a1.y = fmaf(x.y, wa1[t], a1.y);
            a1.z = fmaf(x.z, wa1[t], a1.z);
            a1.w = fmaf(x.w, wa1[t], a1.w);
            a2.x = fmaf(x.x, wa2[t], a2.x);
            a2.y = fmaf(x.y, wa2[t], a2.y);
            a2.z = fmaf(x.z, wa2[t], a2.z);
            a2.w = fmaf(x.w, wa2[t], a2.w);
        }
        int wl = w & 31, whf = w >> 5;
        int vb = v4 * 4;
        ((float*)&sE1p[(vb + 0) * 33 + wl])[whf] = a1.x;
        ((float*)&sE1p[(vb + 1) * 33 + wl])[whf] = a1.y;
        ((float*)&sE1p[(vb + 2) * 33 + wl])[whf] = a1.z;
        ((float*)&sE1p[(vb + 3) * 33 + wl])[whf] = a1.w;
        ((float*)&sE2p[(vb + 0) * 33 + wl])[whf] = a2.x;
        ((float*)&sE2p[(vb + 1) * 33 + wl])[whf] = a2.y;
        ((float*)&sE2p[(vb + 2) * 33 + wl])[whf] = a2.z;
        ((float*)&sE2p[(vb + 3) * 33 + wl])[whf] = a2.w;
    }
    __syncthreads();

    // -------- Phase 2: att_sum[i][w] = sum_j softmax_w(leaky(e1[i]+e2[j])) --------
    {
        unsigned long long E1p[4], att2[4];
#pragma unroll
        for (int ii = 0; ii < 4; ii++) {
            E1p[ii] = *(const unsigned long long*)&sE1p[(warp + ii * 8) * 33 + lane];
            att2[ii] = 0ull;
        }
        const unsigned long long DUP02 = pk2(0.2f, 0.2f);

        for (int j = 0; j < 32; j++) {
            unsigned long long e2 = *(const unsigned long long*)&sE2p[j * 33 + lane];
            unsigned long long T2[4];
            float Z[4];
#pragma unroll
            for (int ii = 0; ii < 4; ii++) {
                unsigned long long x2 = fadd2(E1p[ii], e2);
                unsigned long long m2 = fmul2(x2, DUP02);
                float x0, x1, m0, m1;
                upk2(x2, x0, x1);
                upk2(m2, m0, m1);
                x0 = fmaxf(x0, m0);  // leaky relu (log2-scaled domain)
                x1 = fmaxf(x1, m1);
                float t0 = ex2f(x0);
                float t1 = ex2f(x1);
                T2[ii] = pk2(t0, t1);
                Z[ii] = t0 + t1;
            }
            // 4 independent scalar butterflies, advanced level-by-level (ILP=4)
#pragma unroll
            for (int off = 16; off > 0; off >>= 1) {
#pragma unroll
                for (int ii = 0; ii < 4; ii++)
                    Z[ii] += __shfl_xor_sync(0xffffffffu, Z[ii], off);
            }
#pragma unroll
            for (int ii = 0; ii < 4; ii++) {
                float inv = rcpf(Z[ii]);
                att2[ii] = ffma2(T2[ii], pk2(inv, inv), att2[ii]);
            }
        }
#pragma unroll
        for (int ii = 0; ii < 4; ii++)
            *(unsigned long long*)&sSp[(warp + ii * 8) * 33 + lane] = att2[ii];
    }
    __syncthreads();

    // -------- Phase 3: out[o,u] = sum_t Wt[o,t] * (sum_v hs[w,t,v]*adj[v,u]) --------
    // adjacency column -> registers (conflict-free LDS, lane = u)
    float adjc[32];
#pragma unroll
    for (int v = 0; v < 32; v++) adjc[v] = sAdj[v * 33 + lane];

    float2* myhs = sHS + warp * 32 * 6;

    for (int k = 0; k < 8; k++) {
        int w = warp * 8 + k;
        float sv = ((const float*)&sSp[lane * 33 + (w & 31)])[w >> 5];
        const float* hw = hblk + w * 256 + lane;
        float hs0 = __ldg(hw + 0 * 32) * sv;
        float hs1 = __ldg(hw + 1 * 32) * sv;
        float hs2 = __ldg(hw + 2 * 32) * sv;
        float hs3 = __ldg(hw + 3 * 32) * sv;
        float hs4 = __ldg(hw + 4 * 32) * sv;
        float hs5 = __ldg(hw + 5 * 32) * sv;
        float hs6 = __ldg(hw + 6 * 32) * sv;
        float hs7 = __ldg(hw + 7 * 32) * sv;
        *(float4*)(myhs + lane * 6) = make_float4(hs0, hs4, hs1, hs5);
        *(float4*)(myhs + lane * 6 + 2) = make_float4(hs2, hs6, hs3, hs7);
        __syncwarp();

        unsigned long long g0 = 0ull, g1 = 0ull, g2 = 0ull, g3 = 0ull;
#pragma unroll
        for (int v = 0; v < 32; v++) {
            ulonglong2 q0 = *(const ulonglong2*)(myhs + v * 6);
            ulonglong2 q1 = *(const ulonglong2*)(myhs + v * 6 + 2);
            unsigned long long ad = pk2(adjc[v], adjc[v]);
            g0 = ffma2(q0.x, ad, g0);  // (t0,t4)
            g1 = ffma2(q0.y, ad, g1);  // (t1,t5)
            g2 = ffma2(q1.x, ad, g2);  // (t2,t6)
            g3 = ffma2(q1.y, ad, g3);  // (t3,t7)
        }
        float G0, G1, G2, G3, G4, G5, G6, G7;
        upk2(g0, G0, G4);
        upk2(g1, G1, G5);
        upk2(g2, G2, G6);
        upk2(g3, G3, G7);
        unsigned long long dG[8];
        dG[0] = pk2(G0, G0); dG[1] = pk2(G1, G1);
        dG[2] = pk2(G2, G2); dG[3] = pk2(G3, G3);
        dG[4] = pk2(G4, G4); dG[5] = pk2(G5, G5);
        dG[6] = pk2(G6, G6); dG[7] = pk2(G7, G7);

        float* op = out + ((size_t)(n * 64 + w) * 64 + hh) * 512 + lane;
#pragma unroll
        for (int o2 = 0; o2 < 8; o2++) {
            const ulonglong2* wt = (const ulonglong2*)(sWtp + o2 * 8);
            ulonglong2 wA = wt[0], wB = wt[1], wC = wt[2], wD = wt[3];
            unsigned long long acc = fmul2(dG[0], wA.x);
            acc = ffma2(dG[1], wA.y, acc);
            acc = ffma2(dG[2], wB.x, acc);
            acc = ffma2(dG[3], wB.y, acc);
            acc = ffma2(dG[4], wC.x, acc);
            acc = ffma2(dG[5], wC.y, acc);
            acc = ffma2(dG[6], wD.x, acc);
            acc = ffma2(dG[7], wD.y, acc);
            float r0, r1;
            upk2(acc, r0, r1);
            float e0 = r0 > 0.0f ? r0 : ex2f(r0 * LOG2E) - 1.0f;  // elu
            float e1 = r1 > 0.0f ? r1 : ex2f(r1 * LOG2E) - 1.0f;
            op[(2 * o2) * 32] = e0;
            op[(2 * o2 + 1) * 32] = e1;
        }
        __syncwarp();
    }
}

extern "C" void kernel_launch(void* const* d_in, const int* in_sizes, int n_in,
                              void* d_out, int out_size) {
    const float* h = (const float*)d_in[0];   // (8,64,64,8,32)
    const float* W = (const float*)d_in[1];   // (8,16)
    const float* a = (const float*)d_in[2];   // (32,1)
    const float* Bp = (const float*)d_in[3];  // (32,32)
    float* out = (float*)d_out;               // (8,64,64,16,32)

    dim3 grid(64, 8);
    gat_main<<<grid, 256>>>(h, W, a, Bp, out);
}

// round 9
// speedup vs baseline: 1.2856x; 1.0263x over previous
#include <cuda_runtime.h>
#include <cstdint>

#define LOG2E 1.4426950408889634f

// ---- f32x2 packed helpers (sm_100a) ----
__device__ __forceinline__ unsigned long long pk2(float lo, float hi) {
    unsigned long long r;
    asm("mov.b64 %0, {%1, %2};" : "=l"(r) : "f"(lo), "f"(hi));
    return r;
}
__device__ __forceinline__ void upk2(unsigned long long v, float& lo, float& hi) {
    asm("mov.b64 {%0, %1}, %2;" : "=f"(lo), "=f"(hi) : "l"(v));
}
__device__ __forceinline__ unsigned long long ffma2(unsigned long long a,
                                                    unsigned long long b,
                                                    unsigned long long c) {
    unsigned long long d;
    asm("fma.rn.f32x2 %0, %1, %2, %3;" : "=l"(d) : "l"(a), "l"(b), "l"(c));
    return d;
}
__device__ __forceinline__ unsigned long long fadd2(unsigned long long a,
                                                    unsigned long long b) {
    unsigned long long d;
    asm("add.rn.f32x2 %0, %1, %2;" : "=l"(d) : "l"(a), "l"(b));
    return d;
}
__device__ __forceinline__ unsigned long long fmul2(unsigned long long a,
                                                    unsigned long long b) {
    unsigned long long d;
    asm("mul.rn.f32x2 %0, %1, %2;" : "=l"(d) : "l"(a), "l"(b));
    return d;
}
__device__ __forceinline__ float ex2f(float x) {
    float r;
    asm("ex2.approx.f32 %0, %1;" : "=f"(r) : "f"(x));
    return r;
}
__device__ __forceinline__ float rcpf(float x) {
    float r;
    asm("rcp.approx.f32 %0, %1;" : "=f"(r) : "f"(x));
    return r;
}
__device__ __forceinline__ float rsqf(float x) {
    float r;
    asm("rsqrt.approx.f32 %0, %1;" : "=f"(r) : "f"(x));
    return r;
}

__global__ __launch_bounds__(256)
void gat_main(const float* __restrict__ h, const float* __restrict__ W,
              const float* __restrict__ a, const float* __restrict__ Bp,
              float* __restrict__ out) {
    // paired layouts: [v][wlow] float2 = (val@w, val@w+32), pitch 33 float2
    __shared__ float2 sE1p[32 * 33];
    __shared__ float2 sE2p[32 * 33];
    __shared__ float2 sSp[32 * 33];
    // per-warp hs staging: [v] stride 6 float2; slots = (t,t+4) pairs
    __shared__ __align__(16) float2 sHS[8 * 32 * 6];
    // Wt pre-paired over o-pairs: sWtp[op*8+t] = (W[t,2op], W[t,2op+1])
    __shared__ __align__(16) unsigned long long sWtp[64];
    __shared__ float sWa[16];   // (W@a1, W@a2) per t, *LOG2E
    __shared__ float sAdj[32 * 33];  // normalized adjacency, [v][u], pitch 33
    __shared__ float sRedMin[8], sRedMax[8];

    const int tid = threadIdx.x;
    const int lane = tid & 31;
    const int warp = tid >> 5;
    const int hh = blockIdx.x;
    const int n = blockIdx.y;

    const float* hblk = h + ((size_t)(n * 64 + hh)) * 16384;  // [w][t][v]

    // ---- inline setup A: Wt pairs + Wa ----
    if (tid < 64) {
        int op = tid >> 3, t = tid & 7;
        float2 wp = *(const float2*)(W + t * 16 + 2 * op);
        sWtp[tid] = pk2(wp.x, wp.y);
    }
    if (tid < 16) {
        int which = tid >> 3, t = tid & 7;
        float acc = 0.0f;
#pragma unroll
        for (int o = 0; o < 16; o++) acc += W[t * 16 + o] * a[which * 16 + o];
        sWa[tid] = acc * LOG2E;  // pre-scale so exp() becomes bare ex2
    }

    // ---- inline setup B: adjacency, cooperative + coalesced ----
    {
        // 1 float4 per thread: elements 4*tid .. 4*tid+3; row = tid>>3
        float4 bq = __ldg((const float4*)Bp + tid);
        int row = tid >> 3;
        int c0 = (tid & 7) * 4;
        bq.x += (c0 + 0 == row) ? 1.0f : 0.0f;
        bq.y += (c0 + 1 == row) ? 1.0f : 0.0f;
        bq.z += (c0 + 2 == row) ? 1.0f : 0.0f;
        bq.w += (c0 + 3 == row) ? 1.0f : 0.0f;
        // stash raw values (pitch-33 rows; 4-col groups stay in-row)
        sAdj[row * 33 + c0 + 0] = bq.x;
        sAdj[row * 33 + c0 + 1] = bq.y;
        sAdj[row * 33 + c0 + 2] = bq.z;
        sAdj[row * 33 + c0 + 3] = bq.w;

        float mn = fminf(fminf(bq.x, bq.y), fminf(bq.z, bq.w));
        float mx = fmaxf(fmaxf(bq.x, bq.y), fmaxf(bq.z, bq.w));
#pragma unroll
        for (int off = 16; off > 0; off >>= 1) {
            mn = fminf(mn, __shfl_xor_sync(0xffffffffu, mn, off));
            mx = fmaxf(mx, __shfl_xor_sync(0xffffffffu, mx, off));
        }
        if (lane == 0) {
            sRedMin[warp] = mn;
            sRedMax[warp] = mx;
        }
        __syncthreads();
        float m0 = sRedMin[lane & 7], m1 = sRedMax[lane & 7];
#pragma unroll
        for (int off = 4; off > 0; off >>= 1) {
            m0 = fminf(m0, __shfl_xor_sync(0xffffffffu, m0, off));
            m1 = fmaxf(m1, __shfl_xor_sync(0xffffffffu, m1, off));
        }
        mn = m0;
        mx = m1;
        float scale = rcpf(mx - mn);

        // row sums (raw) — lane = row, conflict-free stride-33 LDS; all warps redundant
        float rsum = 0.0f;
#pragma unroll 8
        for (int k = 0; k < 32; k++) rsum += sAdj[lane * 33 + k];
        float dinv_l = rsqf((rsum - 32.0f * mn) * scale);

        // normalize this thread's 4 entries
        float dv_r = __shfl_sync(0xffffffffu, dinv_l, row & 31);
        float dv0 = __shfl_sync(0xffffffffu, dinv_l, c0 + 0);
        float dv1 = __shfl_sync(0xffffffffu, dinv_l, c0 + 1);
        float dv2 = __shfl_sync(0xffffffffu, dinv_l, c0 + 2);
        float dv3 = __shfl_sync(0xffffffffu, dinv_l, c0 + 3);
        __syncthreads();  // everyone done reading raw sAdj rows
        sAdj[row * 33 + c0 + 0] = dv_r * ((bq.x - mn) * scale) * dv0;
        sAdj[row * 33 + c0 + 1] = dv_r * ((bq.y - mn) * scale) * dv1;
        sAdj[row * 33 + c0 + 2] = dv_r * ((bq.z - mn) * scale) * dv2;
        sAdj[row * 33 + c0 + 3] = dv_r * ((bq.w - mn) * scale) * dv3;
    }
    __syncthreads();

    float wa1[8], wa2[8];
#pragma unroll
    for (int t = 0; t < 8; t++) {
        wa1[t] = sWa[t];
        wa2[t] = sWa[8 + t];
    }

    // -------- Phase 1: e1/e2 = h . (W a * log2e) over t --------
#pragma unroll
    for (int r = 0; r < 2; r++) {
        int qi = tid + 256 * r;  // 0..511
        int w = qi >> 3;
        int v4 = qi & 7;
        const float4* p = (const float4*)(hblk + w * 256 + v4 * 4);
        float4 a1 = make_float4(0.f, 0.f, 0.f, 0.f);
        float4 a2 = make_float4(0.f, 0.f, 0.f, 0.f);
#pragma unroll
        for (int t = 0; t < 8; t++) {
            float4 x = __ldg(p + t * 8);
            a1.x = fmaf(x.x, wa1[t], a1.x);
            a1.y = fmaf(x.y, wa1[t], a1.y);
            a1.z = fmaf(x.z, wa1[t], a1.z);
            a1.w = fmaf(x.w, wa1[t], a1.w);
            a2.x = fmaf(x.x, wa2[t], a2.x);
            a2.y = fmaf(x.y, wa2[t], a2.y);
            a2.z = fmaf(x.z, wa2[t], a2.z);
            a2.w = fmaf(x.w, wa2[t], a2.w);
        }
        int wl = w & 31, whf = w >> 5;
        int vb = v4 * 4;
        ((float*)&sE1p[(vb + 0) * 33 + wl])[whf] = a1.x;
        ((float*)&sE1p[(vb + 1) * 33 + wl])[whf] = a1.y;
        ((float*)&sE1p[(vb + 2) * 33 + wl])[whf] = a1.z;
        ((float*)&sE1p[(vb + 3) * 33 + wl])[whf] = a1.w;
        ((float*)&sE2p[(vb + 0) * 33 + wl])[whf] = a2.x;
        ((float*)&sE2p[(vb + 1) * 33 + wl])[whf] = a2.y;
        ((float*)&sE2p[(vb + 2) * 33 + wl])[whf] = a2.z;
        ((float*)&sE2p[(vb + 3) * 33 + wl])[whf] = a2.w;
    }
    __syncthreads();

    // -------- Phase 2: att_sum[i][w] = sum_j softmax_w(leaky(e1[i]+e2[j])) --------
    // warp owns i = warp + ii*8; lane covers (w=lane, w=lane+32) as f32x2.
    // Packed butterfly: 2 chains over (Z0,Z1) and (Z2,Z3).
    {
        unsigned long long E1p[4], att2[4];
#pragma unroll
        for (int ii = 0; ii < 4; ii++) {
            E1p[ii] = *(const unsigned long long*)&sE1p[(warp + ii * 8) * 33 + lane];
            att2[ii] = 0ull;
        }
        const unsigned long long DUP02 = pk2(0.2f, 0.2f);

        for (int j = 0; j < 32; j++) {
            unsigned long long e2 = *(const unsigned long long*)&sE2p[j * 33 + lane];
            unsigned long long T2[4];
            float Z[4];
#pragma unroll
            for (int ii = 0; ii < 4; ii++) {
                unsigned long long x2 = fadd2(E1p[ii], e2);
                unsigned long long m2 = fmul2(x2, DUP02);
                float x0, x1, m0, m1;
                upk2(x2, x0, x1);
                upk2(m2, m0, m1);
                x0 = fmaxf(x0, m0);  // leaky relu (log2-scaled domain)
                x1 = fmaxf(x1, m1);
                float t0 = ex2f(x0);
                float t1 = ex2f(x1);
                T2[ii] = pk2(t0, t1);
                Z[ii] = t0 + t1;
            }
#pragma unroll
            for (int p = 0; p < 2; p++) {
                unsigned long long z2 = pk2(Z[2 * p], Z[2 * p + 1]);
#pragma unroll
                for (int off = 16; off > 0; off >>= 1)
                    z2 = fadd2(z2, __shfl_xor_sync(0xffffffffu, z2, off));
                float zz0, zz1;
                upk2(z2, zz0, zz1);
                float i0 = rcpf(zz0);
                float i1 = rcpf(zz1);
                att2[2 * p] = ffma2(T2[2 * p], pk2(i0, i0), att2[2 * p]);
                att2[2 * p + 1] = ffma2(T2[2 * p + 1], pk2(i1, i1), att2[2 * p + 1]);
            }
        }
#pragma unroll
        for (int ii = 0; ii < 4; ii++)
            *(unsigned long long*)&sSp[(warp + ii * 8) * 33 + lane] = att2[ii];
    }
    __syncthreads();

    // -------- Phase 3: out[o,u] = sum_t Wt[o,t] * (sum_v hs[w,t,v]*adj[v,u]) --------
    // adjacency column -> registers (conflict-free LDS, lane = u)
    float adjc[32];
#pragma unroll
    for (int v = 0; v < 32; v++) adjc[v] = sAdj[v * 33 + lane];

    float2* myhs = sHS + warp * 32 * 6;

    for (int k = 0; k < 8; k++) {
        int w = warp * 8 + k;
        float sv = ((const float*)&sSp[lane * 33 + (w & 31)])[w >> 5];
        const float* hw = hblk + w * 256 + lane;
        float hs0 = __ldg(hw + 0 * 32) * sv;
        float hs1 = __ldg(hw + 1 * 32) * sv;
        float hs2 = __ldg(hw + 2 * 32) * sv;
        float hs3 = __ldg(hw + 3 * 32) * sv;
        float hs4 = __ldg(hw + 4 * 32) * sv;
        float hs5 = __ldg(hw + 5 * 32) * sv;
        float hs6 = __ldg(hw + 6 * 32) * sv;
        float hs7 = __ldg(hw + 7 * 32) * sv;
        *(float4*)(myhs + lane * 6) = make_float4(hs0, hs4, hs1, hs5);
        *(float4*)(myhs + lane * 6 + 2) = make_float4(hs2, hs6, hs3, hs7);
        __syncwarp();

        unsigned long long g0 = 0ull, g1 = 0ull, g2 = 0ull, g3 = 0ull;
#pragma unroll
        for (int v = 0; v < 32; v++) {
            ulonglong2 q0 = *(const ulonglong2*)(myhs + v * 6);
            ulonglong2 q1 = *(const ulonglong2*)(myhs + v * 6 + 2);
            unsigned long long ad = pk2(adjc[v], adjc[v]);
            g0 = ffma2(q0.x, ad, g0);  // (t0,t4)
            g1 = ffma2(q0.y, ad, g1);  // (t1,t5)
            g2 = ffma2(q1.x, ad, g2);  // (t2,t6)
            g3 = ffma2(q1.y, ad, g3);  // (t3,t7)
        }
        float G0, G1, G2, G3, G4, G5, G6, G7;
        upk2(g0, G0, G4);
        upk2(g1, G1, G5);
        upk2(g2, G2, G6);
        upk2(g3, G3, G7);
        unsigned long long dG[8];
        dG[0] = pk2(G0, G0); dG[1] = pk2(G1, G1);
        dG[2] = pk2(G2, G2); dG[3] = pk2(G3, G3);
        dG[4] = pk2(G4, G4); dG[5] = pk2(G5, G5);
        dG[6] = pk2(G6, G6); dG[7] = pk2(G7, G7);

        float* op = out + ((size_t)(n * 64 + w) * 64 + hh) * 512 + lane;
#pragma unroll
        for (int o2 = 0; o2 < 8; o2++) {
            const ulonglong2* wt = (const ulonglong2*)(sWtp + o2 * 8);
            ulonglong2 wA = wt[0], wB = wt[1], wC = wt[2], wD = wt[3];
            unsigned long long acc = fmul2(dG[0], wA.x);
            acc = ffma2(dG[1], wA.y, acc);
            acc = ffma2(dG[2], wB.x, acc);
            acc = ffma2(dG[3], wB.y, acc);
            acc = ffma2(dG[4], wC.x, acc);
            acc = ffma2(dG[5], wC.y, acc);
            acc = ffma2(dG[6], wD.x, acc);
            acc = ffma2(dG[7], wD.y, acc);
            float r0, r1;
            upk2(acc, r0, r1);
            float e0 = r0 > 0.0f ? r0 : ex2f(r0 * LOG2E) - 1.0f;  // elu
            float e1 = r1 > 0.0f ? r1 : ex2f(r1 * LOG2E) - 1.0f;
            op[(2 * o2) * 32] = e0;
            op[(2 * o2 + 1) * 32] = e1;
        }
        __syncwarp();
    }
}

extern "C" void kernel_launch(void* const* d_in, const int* in_sizes, int n_in,
                              void* d_out, int out_size) {
    const float* h = (const float*)d_in[0];   // (8,64,64,8,32)
    const float* W = (const float*)d_in[1];   // (8,16)
    const float* a = (const float*)d_in[2];   // (32,1)
    const float* Bp = (const float*)d_in[3];  // (32,32)
    float* out = (float*)d_out;               // (8,64,64,16,32)

    dim3 grid(64, 8);
    gat_main<<<grid, 256>>>(h, W, a, Bp, out);
}